// round 2
// baseline (speedup 1.0000x reference)
#include <cuda_runtime.h>

#define CC 64
#define BB 32
#define HH 80
#define WW 80
#define CELL (CC*BB)      // 2048 floats per cell tile
#define NCELLS (HH*WW)    // 6400 cells

// Static device scratch (allocation-free per harness rules)
__device__ float g_xT[NCELLS*CELL];          // x transposed to [i][j][c][b]
__device__ float g_hf[4][NCELLS*CELL];       // per-direction h fields, [i][j][c][b]
__device__ int   g_cnt[4][WW];               // rows completed per (dir, internal column)

typedef unsigned long long ull;

// ---------- packed-f32x2 helpers (B300: FFMA2 only reachable via PTX) ----------
static __device__ __forceinline__ ull splat2(float x){
  unsigned int r = __float_as_uint(x);
  ull d; asm("mov.b64 %0, {%1,%2};" : "=l"(d) : "r"(r), "r"(r));
  return d;
}
static __device__ __forceinline__ void fma2(ull &d, ull a, ull b){
  asm("fma.rn.f32x2 %0, %1, %2, %0;" : "+l"(d) : "l"(a), "l"(b));
}
static __device__ __forceinline__ void unpack2(ull v, float &lo, float &hi){
  unsigned int a, b;
  asm("mov.b64 {%0,%1}, %2;" : "=r"(a), "=r"(b) : "l"(v));
  lo = __uint_as_float(a); hi = __uint_as_float(b);
}
static __device__ __forceinline__ int ld_acq(const int* p){
  int v; asm volatile("ld.global.acquire.gpu.b32 %0, [%1];" : "=r"(v) : "l"(p)); return v;
}
static __device__ __forceinline__ void st_rel(int* p, int v){
  asm volatile("st.global.release.gpu.b32 [%0], %1;" :: "l"(p), "r"(v));
}

// ---------- kernel 1: transpose x [B,C,H,W] -> g_xT [i][j][c][b]; also zero flags ----------
__global__ void __launch_bounds__(256) k_transpose(const float* __restrict__ x){
  int bid = blockIdx.x;              // 800 blocks: (i, j-tile of 8)
  int i  = bid / 10;
  int j0 = (bid % 10) * 8;
  int t  = threadIdx.x;

  if (bid == 0 && t < 4*WW) ((int*)g_cnt)[t] = 0;

  int p0 = t * 8;                    // p = c*32 + b ; 8 consecutive p = fixed c, 8 b's
  int c  = p0 >> 5;
  int b0 = p0 & 31;

  float v[8][8];
  #pragma unroll
  for (int pi = 0; pi < 8; pi++){
    const float* src = x + (((b0+pi)*CC + c)*HH + i)*WW + j0;
    float4 q0 = *(const float4*)src;
    float4 q1 = *(const float4*)(src + 4);
    v[pi][0]=q0.x; v[pi][1]=q0.y; v[pi][2]=q0.z; v[pi][3]=q0.w;
    v[pi][4]=q1.x; v[pi][5]=q1.y; v[pi][6]=q1.z; v[pi][7]=q1.w;
  }
  #pragma unroll
  for (int jj = 0; jj < 8; jj++){
    float* dst = g_xT + (i*WW + j0 + jj)*CELL + p0;
    *(float4*)dst     = make_float4(v[0][jj], v[1][jj], v[2][jj], v[3][jj]);
    *(float4*)(dst+4) = make_float4(v[4][jj], v[5][jj], v[6][jj], v[7][jj]);
  }
}

// ---------- inner matmul: acc(4c x 2b per thread) += G(64x64, transposed in smem) @ hbuf(64x32) ----------
static __device__ __forceinline__ void mm_acc(const float* sG, const float* hbuf,
    int c0, int b0, ull &a00, ull &a01, ull &a10, ull &a11){
  #pragma unroll 8
  for (int k = 0; k < CC; k++){
    ulonglong2 g = *(const ulonglong2*)(sG + k*CC + c0);   // {G[c0,k],G[c0+1,k]},{G[c0+2,k],G[c0+3,k]}
    float2 hh = *(const float2*)(hbuf + k*BB + b0);        // h[k, b0], h[k, b0+1]
    ull s0 = splat2(hh.x), s1 = splat2(hh.y);
    fma2(a00, g.x, s0); fma2(a01, g.y, s0);
    fma2(a10, g.x, s1); fma2(a11, g.y, s1);
  }
}

// ---------- kernel 2: persistent column-pipelined DAG recurrence, 4 dirs x 80 columns ----------
extern __shared__ float smem_dyn[];

__global__ void __launch_bounds__(256, 3) k_dag(
    const float* __restrict__ w0v, const float* __restrict__ w0h,
    const float* __restrict__ w1v, const float* __restrict__ w1h,
    const float* __restrict__ w2v, const float* __restrict__ w2h,
    const float* __restrict__ w3v, const float* __restrict__ w3h)
{
  const int bid  = blockIdx.x;
  const int dir  = bid / WW;        // dependency points to lower bids only -> schedule-safe
  const int jcol = bid % WW;
  const int tid  = threadIdx.x;

  const float* gv; const float* gh;
  int fi, fj, doRelu;
  switch (dir){
    case 0:  gv=w0v; gh=w0h; fi=0; fj=0; doRelu=1; break;  // SE
    case 1:  gv=w1v; gh=w1h; fi=1; fj=0; doRelu=1; break;  // NE
    case 2:  gv=w2v; gh=w2h; fi=1; fj=1; doRelu=1; break;  // NW
    default: gv=w3v; gh=w3h; fi=0; fj=1; doRelu=0; break;  // SW (no ReLU in reference)
  }

  float* sGv = smem_dyn;                  // [k][c] transposed, 4096 f
  float* sGh = smem_dyn + 4096;           // [k][c] transposed, 4096 f
  float* hA  = smem_dyn + 8192;           // h_prev (vertical neighbor), [k][b]
  float* hB  = smem_dyn + 8192 + CELL;    // h_left staging,            [k][b]

  for (int idx = tid; idx < 4096; idx += 256){
    int c = idx >> 6, k = idx & 63;       // idx = c*64 + k (row-major source)
    sGv[k*CC + c] = gv[idx];
    sGh[k*CC + c] = gh[idx];
  }
  for (int idx = tid; idx < CELL; idx += 256) hA[idx] = 0.f;
  __syncthreads();

  const int cg = tid & 15, bg = tid >> 4;
  const int c0 = cg * 4, b0 = bg * 2;

  float* out_dir = g_hf[dir];
  const int rj  = fj ? (WW-1-jcol) : jcol;          // actual column of this internal column
  const int rjL = fj ? (WW-jcol)   : (jcol-1);      // actual column of internal (j-1)
  const int* cleft = &g_cnt[dir][(jcol > 0) ? (jcol-1) : 0];
  int* cme = &g_cnt[dir][jcol];

  for (int i = 0; i < HH; i++){
    const int ri = fi ? (HH-1-i) : i;
    const float* xcell = g_xT + (ri*WW + rj)*CELL;

    // prefetch x for this cell (consumed ~2000 cycles later)
    float2 xv0 = *(const float2*)(xcell + (c0+0)*BB + b0);
    float2 xv1 = *(const float2*)(xcell + (c0+1)*BB + b0);
    float2 xv2 = *(const float2*)(xcell + (c0+2)*BB + b0);
    float2 xv3 = *(const float2*)(xcell + (c0+3)*BB + b0);

    ull a00 = 0, a01 = 0, a10 = 0, a11 = 0;

    // vertical matmul: Gv @ h_prev (in-CTA, SMEM-resident)
    mm_acc(sGv, hA, c0, b0, a00, a01, a10, a11);

    // horizontal handoff from column j-1
    if (jcol > 0){
      const int need = i + 1;
      if (ld_acq(cleft) < need){
        while (ld_acq(cleft) < need) __nanosleep(64);
      }
      const float* lcell = out_dir + (ri*WW + rjL)*CELL;
      float4 l0 = *(const float4*)(lcell + tid*8);
      float4 l1 = *(const float4*)(lcell + tid*8 + 4);
      *(float4*)(hB + tid*8)     = l0;
      *(float4*)(hB + tid*8 + 4) = l1;
    }
    __syncthreads();                       // hB ready; everyone done reading hA (matmul1)

    if (jcol > 0){
      mm_acc(sGh, hB, c0, b0, a00, a01, a10, a11);
    }

    // epilogue: unpack, +x, (ReLU)
    float oc[4][2];
    unpack2(a00, oc[0][0], oc[1][0]);
    unpack2(a01, oc[2][0], oc[3][0]);
    unpack2(a10, oc[0][1], oc[1][1]);
    unpack2(a11, oc[2][1], oc[3][1]);
    oc[0][0] += xv0.x; oc[0][1] += xv0.y;
    oc[1][0] += xv1.x; oc[1][1] += xv1.y;
    oc[2][0] += xv2.x; oc[2][1] += xv2.y;
    oc[3][0] += xv3.x; oc[3][1] += xv3.y;
    if (doRelu){
      #pragma unroll
      for (int r = 0; r < 4; r++){
        oc[r][0] = fmaxf(oc[r][0], 0.f);
        oc[r][1] = fmaxf(oc[r][1], 0.f);
      }
    }

    // h -> hA (becomes h_prev for next row)
    #pragma unroll
    for (int r = 0; r < 4; r++)
      *(float2*)(hA + (c0+r)*BB + b0) = make_float2(oc[r][0], oc[r][1]);
    __syncthreads();                       // hA tile complete

    // coalesced publish of the full tile for the right neighbor + final sum
    float* ocell = out_dir + (ri*WW + rj)*CELL;
    *(float4*)(ocell + tid*8)     = *(const float4*)(hA + tid*8);
    *(float4*)(ocell + tid*8 + 4) = *(const float4*)(hA + tid*8 + 4);
    __threadfence();                       // every thread fences its own stores
    __syncthreads();                       // all fences done
    if (tid == 0) st_rel(cme, i + 1);      // release counter for column j
  }
}

// ---------- kernel 3: out[b][c][i][j] = sum over 4 dirs of g_hf[d][i][j][c][b] ----------
__global__ void __launch_bounds__(256) k_sum(float* __restrict__ out){
  int bid = blockIdx.x;              // 800 blocks: (i, j-tile of 8)
  int i  = bid / 10;
  int j0 = (bid % 10) * 8;
  int t  = threadIdx.x;
  int p0 = t * 8;                    // fixed c, 8 consecutive b
  int c  = p0 >> 5;
  int b0 = p0 & 31;

  float v[8][8];
  #pragma unroll
  for (int jj = 0; jj < 8; jj++){
    int cell = (i*WW + j0 + jj)*CELL;
    float4 s0 = make_float4(0.f,0.f,0.f,0.f);
    float4 s1 = make_float4(0.f,0.f,0.f,0.f);
    #pragma unroll
    for (int d = 0; d < 4; d++){
      const float* src = g_hf[d] + cell + p0;
      float4 q0 = *(const float4*)src;
      float4 q1 = *(const float4*)(src + 4);
      s0.x += q0.x; s0.y += q0.y; s0.z += q0.z; s0.w += q0.w;
      s1.x += q1.x; s1.y += q1.y; s1.z += q1.z; s1.w += q1.w;
    }
    v[0][jj]=s0.x; v[1][jj]=s0.y; v[2][jj]=s0.z; v[3][jj]=s0.w;
    v[4][jj]=s1.x; v[5][jj]=s1.y; v[6][jj]=s1.z; v[7][jj]=s1.w;
  }
  #pragma unroll
  for (int pi = 0; pi < 8; pi++){
    float* dst = out + ((b0+pi)*CC + c)*NCELLS + i*WW + j0;
    *(float4*)dst     = make_float4(v[pi][0], v[pi][1], v[pi][2], v[pi][3]);
    *(float4*)(dst+4) = make_float4(v[pi][4], v[pi][5], v[pi][6], v[pi][7]);
  }
}

extern "C" void kernel_launch(void* const* d_in, const int* in_sizes, int n_in,
                              void* d_out, int out_size){
  const float* x   = (const float*)d_in[0];
  const float* g1  = (const float*)d_in[1];
  const float* g2  = (const float*)d_in[2];
  const float* g4  = (const float*)d_in[3];
  const float* g5  = (const float*)d_in[4];
  const float* g7  = (const float*)d_in[5];
  const float* g8  = (const float*)d_in[6];
  const float* g10 = (const float*)d_in[7];
  const float* g11 = (const float*)d_in[8];

  (void)cudaFuncSetAttribute(k_dag, cudaFuncAttributeMaxDynamicSharedMemorySize, 49152);

  k_transpose<<<800, 256>>>(x);
  k_dag<<<320, 256, 49152>>>(g1, g2, g4, g5, g7, g8, g10, g11);
  k_sum<<<800, 256>>>((float*)d_out);
}